// round 11
// baseline (speedup 1.0000x reference)
#include <cuda_runtime.h>
#include <cuda_bf16.h>
#include <math.h>
#include <stdint.h>

typedef unsigned short ushort_t;

#define B_    8
#define N_    4096
#define C_    768
#define H_    12
#define HD_   64
#define NWIN_ 16
#define WT_   256
#define C3_   2304
#define M_    (B_ * N_)   /* 32768 */
#define SCALE_ 0.125f

// ---- device globals: everything stored as packed bf16 hi/lo planes ----
__device__ __align__(256) ushort_t g_xh [(size_t)M_ * C_];
__device__ __align__(256) ushort_t g_xl [(size_t)M_ * C_];
__device__ __align__(256) ushort_t g_w1h[(size_t)C3_ * C_];
__device__ __align__(256) ushort_t g_w1l[(size_t)C3_ * C_];
__device__ __align__(256) ushort_t g_w2h[(size_t)C_ * C_];
__device__ __align__(256) ushort_t g_w2l[(size_t)C_ * C_];
__device__ __align__(256) ushort_t g_qkvh[(size_t)M_ * C3_];
__device__ __align__(256) ushort_t g_qkvl[(size_t)M_ * C3_];
__device__ __align__(256) ushort_t g_aoh[(size_t)M_ * C_];
__device__ __align__(256) ushort_t g_aol[(size_t)M_ * C_];

// permuted position p <-> original token index (involution)
__device__ __forceinline__ int perm_orig(int p) {
    int a = p >> 10, c = (p >> 8) & 3, bq = (p >> 4) & 15, d = p & 15;
    return (a << 10) | (bq << 6) | (c << 4) | d;
}

__device__ __forceinline__ uint32_t smem_u32(const void* p) {
    uint32_t a;
    asm("{ .reg .u64 t; cvta.to.shared.u64 t, %1; cvt.u32.u64 %0, t; }" : "=r"(a) : "l"(p));
    return a;
}

#define STS64(a, r0, r1) asm volatile( \
    "st.shared.v2.b32 [%0], {%1, %2};" :: "r"(a), "r"(r0), "r"(r1) : "memory")

#define LDM4(r, addr) asm volatile( \
    "ldmatrix.sync.aligned.m8n8.x4.shared.b16 {%0,%1,%2,%3}, [%4];" \
    : "=r"((r)[0]), "=r"((r)[1]), "=r"((r)[2]), "=r"((r)[3]) : "r"(addr))

#define LDM4T(r, addr) asm volatile( \
    "ldmatrix.sync.aligned.m8n8.x4.trans.shared.b16 {%0,%1,%2,%3}, [%4];" \
    : "=r"((r)[0]), "=r"((r)[1]), "=r"((r)[2]), "=r"((r)[3]) : "r"(addr))

#define MMA16816(c, a, b0, b1) asm volatile( \
    "mma.sync.aligned.m16n8k16.row.col.f32.bf16.bf16.f32 " \
    "{%0,%1,%2,%3}, {%4,%5,%6,%7}, {%8,%9}, {%0,%1,%2,%3};" \
    : "+f"((c)[0]), "+f"((c)[1]), "+f"((c)[2]), "+f"((c)[3]) \
    : "r"((a)[0]), "r"((a)[1]), "r"((a)[2]), "r"((a)[3]), "r"(b0), "r"(b1))

#define CP16(dst, src) asm volatile( \
    "cp.async.ca.shared.global [%0], [%1], 16;" :: "r"(dst), "l"(src) : "memory")
#define CP_COMMIT() asm volatile("cp.async.commit_group;" ::: "memory")
#define CP_WAIT1()  asm volatile("cp.async.wait_group 1;" ::: "memory")
#define CP_WAIT0()  asm volatile("cp.async.wait_group 0;" ::: "memory")

// fp32 -> (hi bf16, lo bf16) packed pair
__device__ __forceinline__ uint32_t pk2(float a, float b) {
    __nv_bfloat16 ha = __float2bfloat16(a), hb = __float2bfloat16(b);
    return (uint32_t)__bfloat16_as_ushort(ha) | ((uint32_t)__bfloat16_as_ushort(hb) << 16);
}
__device__ __forceinline__ void splitpk(float a, float b, uint32_t& hi, uint32_t& lo) {
    __nv_bfloat16 ha = __float2bfloat16(a), hb = __float2bfloat16(b);
    hi = (uint32_t)__bfloat16_as_ushort(ha) | ((uint32_t)__bfloat16_as_ushort(hb) << 16);
    lo = pk2(a - __bfloat162float(ha), b - __bfloat162float(hb));
}

// ---------------------------------------------------------------------------
// fp32 -> hi/lo plane split (pre-pass for x, qkv_w, proj_w)
// ---------------------------------------------------------------------------
__global__ __launch_bounds__(256) void split_k(const float* __restrict__ src,
                                               ushort_t* __restrict__ hi,
                                               ushort_t* __restrict__ lo, int n4)
{
    int i = blockIdx.x * 256 + threadIdx.x;
    if (i < n4) {
        float4 f = reinterpret_cast<const float4*>(src)[i];
        uint32_t h0, h1, l0, l1;
        splitpk(f.x, f.y, h0, l0);
        splitpk(f.z, f.w, h1, l1);
        reinterpret_cast<uint2*>(hi)[i] = make_uint2(h0, h1);
        reinterpret_cast<uint2*>(lo)[i] = make_uint2(l0, l1);
    }
}

// ---------------------------------------------------------------------------
// cp.async double-buffered bf16 3-term-split GEMM.
// C[M x NOUT] = A[M x 768] @ W[NOUT x 768]^T, A/B given as hi/lo planes.
// CTA tile 128x128, BK=16, 48 chunks, 256 threads (8 warps, 64x32 tiles).
// Smem: 2 buffers x 4 planes (Ahi,Alo,Bhi,Blo) of 128 rows x 24-ushort stride.
// MODE 0: permuted A-row reads, output -> qkv hi/lo planes.
// MODE 1: linear A-rows, permuted C stores, + bias, fp32 out.
// ---------------------------------------------------------------------------
#define GTS_ 24          /* smem row stride in ushort (48 B) */
#define PL_  (128 * GTS_ * 2)   /* plane bytes = 6144 */
#define BUF_ (4 * PL_)          /* buffer bytes = 24576 */

template<int NOUT, int MODE>
__global__ __launch_bounds__(256)
void mma_gemm_k(const ushort_t* __restrict__ Ah, const ushort_t* __restrict__ Al,
                const ushort_t* __restrict__ Bh, const ushort_t* __restrict__ Bl,
                const float* __restrict__ bias,
                ushort_t* __restrict__ Oh, ushort_t* __restrict__ Ol,
                float* __restrict__ Cext)
{
    __shared__ __align__(16) ushort_t smem[2 * 4 * 128 * GTS_];  // 48 KB

    const int tid  = threadIdx.x;
    const int wid  = tid >> 5;
    const int lane = tid & 31;
    const int bm   = blockIdx.y * 128;
    const int bn   = blockIdx.x * 128;
    const int wm   = (wid & 1) * 64;
    const int wn   = (wid >> 1) * 32;

    const uint32_t sb = smem_u32(smem);

    // staging assignment: each thread owns (row cr, 16B-chunk cq) in all 4 planes
    const int cr = tid >> 1;
    const int cq = tid & 1;
    int gmA = bm + cr;
    const size_t arow = (size_t)((MODE == 0) ? ((gmA & ~4095) + perm_orig(gmA & 4095)) : gmA) * C_;
    const size_t brow = (size_t)(bn + cr) * C_;
    const uint32_t dstb = sb + (uint32_t)(cr * 48 + cq * 16);

    // ldmatrix per-lane offsets (48-B row stride)
    const int g = lane >> 3, lr = lane & 7;
    const uint32_t aoff = (uint32_t)((lr + (g & 1) * 8) * 48 + (g >> 1) * 16);
    const uint32_t boff = (uint32_t)((lr + (g >> 1) * 8) * 48 + (g & 1) * 16);

    float acc[4][4][4];
    #pragma unroll
    for (int i = 0; i < 4; i++)
        #pragma unroll
        for (int j = 0; j < 4; j++)
            #pragma unroll
            for (int v = 0; v < 4; v++) acc[i][j][v] = 0.f;

    // prologue: stage chunk 0 into buffer 0
    {
        const int koff = cq * 8;
        CP16(dstb,            Ah + arow + koff);
        CP16(dstb + PL_,      Al + arow + koff);
        CP16(dstb + 2 * PL_,  Bh + brow + koff);
        CP16(dstb + 3 * PL_,  Bl + brow + koff);
        CP_COMMIT();
    }

    #pragma unroll 1
    for (int kc = 0; kc < 48; kc++) {
        if (kc < 47) {
            const int koff = (kc + 1) * 16 + cq * 8;
            const uint32_t d = dstb + ((kc + 1) & 1) * BUF_;
            CP16(d,            Ah + arow + koff);
            CP16(d + PL_,      Al + arow + koff);
            CP16(d + 2 * PL_,  Bh + brow + koff);
            CP16(d + 3 * PL_,  Bl + brow + koff);
            CP_COMMIT();
            CP_WAIT1();
        } else {
            CP_WAIT0();
        }
        __syncthreads();

        const uint32_t bb = sb + (kc & 1) * BUF_;
        uint32_t ah[4][4], al[4][4], bh[2][4], bl[2][4];
        #pragma unroll
        for (int mf = 0; mf < 4; mf++) {
            uint32_t base = (uint32_t)((wm + mf * 16) * 48) + aoff;
            LDM4(ah[mf], bb + base);
            LDM4(al[mf], bb + PL_ + base);
        }
        #pragma unroll
        for (int nb = 0; nb < 2; nb++) {
            uint32_t base = (uint32_t)((wn + nb * 16) * 48) + boff;
            LDM4(bh[nb], bb + 2 * PL_ + base);
            LDM4(bl[nb], bb + 3 * PL_ + base);
        }
        #pragma unroll
        for (int mf = 0; mf < 4; mf++)
            #pragma unroll
            for (int nf = 0; nf < 4; nf++) {
                uint32_t* bhp = &bh[nf >> 1][(nf & 1) * 2];
                uint32_t* blp = &bl[nf >> 1][(nf & 1) * 2];
                MMA16816(acc[mf][nf], ah[mf], bhp[0], bhp[1]);
                MMA16816(acc[mf][nf], ah[mf], blp[0], blp[1]);
                MMA16816(acc[mf][nf], al[mf], bhp[0], bhp[1]);
            }
        __syncthreads();
    }

    // ---- epilogue ----
    const int l4 = lane >> 2, l2 = (lane & 3) * 2;
    float2 bb2[4];
    if (MODE == 1) {
        #pragma unroll
        for (int nf = 0; nf < 4; nf++)
            bb2[nf] = *reinterpret_cast<const float2*>(bias + bn + wn + nf * 8 + l2);
    }
    #pragma unroll
    for (int mf = 0; mf < 4; mf++) {
        int gm0 = bm + wm + mf * 16 + l4;
        int gm1 = gm0 + 8;
        int cr0 = (MODE == 1) ? ((gm0 & ~4095) + perm_orig(gm0 & 4095)) : gm0;
        int cr1 = (MODE == 1) ? ((gm1 & ~4095) + perm_orig(gm1 & 4095)) : gm1;
        #pragma unroll
        for (int nf = 0; nf < 4; nf++) {
            int gn = bn + wn + nf * 8 + l2;
            if (MODE == 1) {
                float2 v0, v1;
                v0.x = acc[mf][nf][0] + bb2[nf].x; v0.y = acc[mf][nf][1] + bb2[nf].y;
                v1.x = acc[mf][nf][2] + bb2[nf].x; v1.y = acc[mf][nf][3] + bb2[nf].y;
                *reinterpret_cast<float2*>(Cext + (size_t)cr0 * NOUT + gn) = v0;
                *reinterpret_cast<float2*>(Cext + (size_t)cr1 * NOUT + gn) = v1;
            } else {
                uint32_t h, l;
                splitpk(acc[mf][nf][0], acc[mf][nf][1], h, l);
                *reinterpret_cast<uint32_t*>(Oh + (size_t)cr0 * NOUT + gn) = h;
                *reinterpret_cast<uint32_t*>(Ol + (size_t)cr0 * NOUT + gn) = l;
                splitpk(acc[mf][nf][2], acc[mf][nf][3], h, l);
                *reinterpret_cast<uint32_t*>(Oh + (size_t)cr1 * NOUT + gn) = h;
                *reinterpret_cast<uint32_t*>(Ol + (size_t)cr1 * NOUT + gn) = l;
            }
        }
    }
}

// ---------------------------------------------------------------------------
// Tensor-core windowed attention (pre-split planes; no cvt in staging).
// Block = 256 threads, 128 queries of one (b,w,h); keys in 4 chunks of 64.
// S scaled by SCALE_ post-MMA (exact: 2^-3). Epilogue writes hi/lo planes.
// ---------------------------------------------------------------------------
#define SQT_ 72          /* bf16 row stride (144 B) */

__global__ __launch_bounds__(256) void attn_k()
{
    __shared__ __align__(16) ushort_t smb[18432];  // 36.9 KB

    const int tid = threadIdx.x, wid = tid >> 5, lane = tid & 31;
    const int blk = blockIdx.x;
    const int half = blk & 1;
    const int t = blk >> 1;
    const int h = t % H_;
    const int w = (t / H_) % NWIN_;
    const int b = t / (H_ * NWIN_);
    const int rowbase = b * N_ + w * WT_;
    const int qrow0 = rowbase + half * 128;
    const int qoff = h * HD_, koff = C_ + h * HD_, voff = 2 * C_ + h * HD_;

    const uint32_t sb = smem_u32(smb);
    const uint32_t aQhi = sb,            aQlo = sb + 9216 * 2;
    const uint32_t aKhi = sb,            aKlo = sb + 4608 * 2;
    const uint32_t aVhi = sb + 9216 * 2, aVlo = sb + 13824 * 2;

    const int g = lane >> 3, lr = lane & 7;
    const uint32_t aoff = (uint32_t)((lr + (g & 1) * 8) * 144 + (g >> 1) * 16);
    const uint32_t boff = (uint32_t)((lr + (g >> 1) * 8) * 144 + (g & 1) * 16);

    // ---- stage Q from planes ----
    #pragma unroll
    for (int it = 0; it < 8; it++) {
        int idx = it * 256 + tid;
        int r = idx >> 4, gq = idx & 15;
        size_t off_g = (size_t)(qrow0 + r) * C3_ + qoff + gq * 4;
        uint2 hv = *reinterpret_cast<const uint2*>(g_qkvh + off_g);
        uint2 lv = *reinterpret_cast<const uint2*>(g_qkvl + off_g);
        uint32_t off = (uint32_t)(r * SQT_ + gq * 4) * 2;
        STS64(aQhi + off, hv.x, hv.y);
        STS64(aQlo + off, lv.x, lv.y);
    }
    __syncthreads();

    uint32_t qh[4][4], ql[4][4];
    #pragma unroll
    for (int kb = 0; kb < 4; kb++) {
        uint32_t base = (uint32_t)(wid * 16 * 144 + kb * 32) + aoff;
        LDM4(qh[kb], aQhi + base);
        LDM4(ql[kb], aQlo + base);
    }
    __syncthreads();

    float od[8][4];
    #pragma unroll
    for (int j = 0; j < 8; j++)
        #pragma unroll
        for (int v = 0; v < 4; v++) od[j][v] = 0.f;
    float m0 = -1e30f, m1 = -1e30f, l0 = 0.f, l1 = 0.f;

    #pragma unroll 1
    for (int c = 0; c < 4; c++) {
        const int kc = c * 64;
        // ---- stage K and V chunk from planes ----
        #pragma unroll
        for (int it = 0; it < 4; it++) {
            int idx = it * 256 + tid;
            int r = idx >> 4, gq = idx & 15;
            size_t rg = (size_t)(rowbase + kc + r) * C3_;
            uint32_t off = (uint32_t)(r * SQT_ + gq * 4) * 2;
            uint2 hv = *reinterpret_cast<const uint2*>(g_qkvh + rg + koff + gq * 4);
            uint2 lv = *reinterpret_cast<const uint2*>(g_qkvl + rg + koff + gq * 4);
            STS64(aKhi + off, hv.x, hv.y);
            STS64(aKlo + off, lv.x, lv.y);
            hv = *reinterpret_cast<const uint2*>(g_qkvh + rg + voff + gq * 4);
            lv = *reinterpret_cast<const uint2*>(g_qkvl + rg + voff + gq * 4);
            STS64(aVhi + off, hv.x, hv.y);
            STS64(aVlo + off, lv.x, lv.y);
        }
        __syncthreads();

        // ---- S = Q*K^T (3-term split) ----
        float s[8][4];
        #pragma unroll
        for (int j = 0; j < 8; j++)
            #pragma unroll
            for (int v = 0; v < 4; v++) s[j][v] = 0.f;
        #pragma unroll
        for (int kb = 0; kb < 4; kb++) {
            #pragma unroll
            for (int nt = 0; nt < 4; nt++) {
                uint32_t base = (uint32_t)(nt * 16 * 144 + kb * 32);
                uint32_t kh[4], kl[4];
                LDM4(kh, aKhi + base + boff);
                LDM4(kl, aKlo + base + boff);
                MMA16816(s[2 * nt],     qh[kb], kh[0], kh[1]);
                MMA16816(s[2 * nt],     qh[kb], kl[0], kl[1]);
                MMA16816(s[2 * nt],     ql[kb], kh[0], kh[1]);
                MMA16816(s[2 * nt + 1], qh[kb], kh[2], kh[3]);
                MMA16816(s[2 * nt + 1], qh[kb], kl[2], kl[3]);
                MMA16816(s[2 * nt + 1], ql[kb], kh[2], kh[3]);
            }
        }
        #pragma unroll
        for (int j = 0; j < 8; j++)
            #pragma unroll
            for (int v = 0; v < 4; v++) s[j][v] *= SCALE_;

        // ---- online softmax ----
        float cm0 = -1e30f, cm1 = -1e30f;
        #pragma unroll
        for (int j = 0; j < 8; j++) {
            cm0 = fmaxf(cm0, fmaxf(s[j][0], s[j][1]));
            cm1 = fmaxf(cm1, fmaxf(s[j][2], s[j][3]));
        }
        cm0 = fmaxf(cm0, __shfl_xor_sync(0xffffffffu, cm0, 1));
        cm0 = fmaxf(cm0, __shfl_xor_sync(0xffffffffu, cm0, 2));
        cm1 = fmaxf(cm1, __shfl_xor_sync(0xffffffffu, cm1, 1));
        cm1 = fmaxf(cm1, __shfl_xor_sync(0xffffffffu, cm1, 2));
        float mn0 = fmaxf(m0, cm0), mn1 = fmaxf(m1, cm1);
        float corr0 = __expf(m0 - mn0), corr1 = __expf(m1 - mn1);
        m0 = mn0; m1 = mn1;
        float sum0 = 0.f, sum1 = 0.f;
        #pragma unroll
        for (int j = 0; j < 8; j++) {
            s[j][0] = __expf(s[j][0] - mn0);
            s[j][1] = __expf(s[j][1] - mn0);
            s[j][2] = __expf(s[j][2] - mn1);
            s[j][3] = __expf(s[j][3] - mn1);
            sum0 += s[j][0] + s[j][1];
            sum1 += s[j][2] + s[j][3];
        }
        sum0 += __shfl_xor_sync(0xffffffffu, sum0, 1);
        sum0 += __shfl_xor_sync(0xffffffffu, sum0, 2);
        sum1 += __shfl_xor_sync(0xffffffffu, sum1, 1);
        sum1 += __shfl_xor_sync(0xffffffffu, sum1, 2);
        l0 = l0 * corr0 + sum0;
        l1 = l1 * corr1 + sum1;
        #pragma unroll
        for (int j = 0; j < 8; j++) {
            od[j][0] *= corr0; od[j][1] *= corr0;
            od[j][2] *= corr1; od[j][3] *= corr1;
        }

        // ---- O += P*V ----
        #pragma unroll
        for (int kb = 0; kb < 4; kb++) {
            uint32_t ph[4], pl[4];
            splitpk(s[2 * kb][0],     s[2 * kb][1],     ph[0], pl[0]);
            splitpk(s[2 * kb][2],     s[2 * kb][3],     ph[1], pl[1]);
            splitpk(s[2 * kb + 1][0], s[2 * kb + 1][1], ph[2], pl[2]);
            splitpk(s[2 * kb + 1][2], s[2 * kb + 1][3], ph[3], pl[3]);
            #pragma unroll
            for (int dt = 0; dt < 4; dt++) {
                uint32_t base = (uint32_t)(kb * 16 * 144 + dt * 32);
                uint32_t vh[4], vl[4];
                LDM4T(vh, aVhi + base + aoff);
                LDM4T(vl, aVlo + base + aoff);
                MMA16816(od[2 * dt],     ph, vh[0], vh[1]);
                MMA16816(od[2 * dt],     ph, vl[0], vl[1]);
                MMA16816(od[2 * dt],     pl, vh[0], vh[1]);
                MMA16816(od[2 * dt + 1], ph, vh[2], vh[3]);
                MMA16816(od[2 * dt + 1], ph, vl[2], vl[3]);
                MMA16816(od[2 * dt + 1], pl, vh[2], vh[3]);
            }
        }
        __syncthreads();
    }

    // ---- epilogue: normalize + split-store planes ----
    const float inv0 = 1.f / l0, inv1 = 1.f / l1;
    const int r = lane >> 2, tt = lane & 3;
    const int gr0 = qrow0 + wid * 16 + r;
    const int gr1 = gr0 + 8;
    const size_t ob0 = (size_t)gr0 * C_ + h * HD_;
    const size_t ob1 = (size_t)gr1 * C_ + h * HD_;
    #pragma unroll
    for (int j = 0; j < 8; j++) {
        int d = j * 8 + tt * 2;
        uint32_t hh, ll;
        splitpk(od[j][0] * inv0, od[j][1] * inv0, hh, ll);
        *reinterpret_cast<uint32_t*>(g_aoh + ob0 + d) = hh;
        *reinterpret_cast<uint32_t*>(g_aol + ob0 + d) = ll;
        splitpk(od[j][2] * inv1, od[j][3] * inv1, hh, ll);
        *reinterpret_cast<uint32_t*>(g_aoh + ob1 + d) = hh;
        *reinterpret_cast<uint32_t*>(g_aol + ob1 + d) = ll;
    }
}

// ---------------------------------------------------------------------------

extern "C" void kernel_launch(void* const* d_in, const int* in_sizes, int n_in,
                              void* d_out, int out_size)
{
    const float* x      = (const float*)d_in[0];
    const float* qkv_w  = (const float*)d_in[1];
    const float* proj_w = (const float*)d_in[2];
    const float* proj_b = (const float*)d_in[3];
    float* out = (float*)d_out;

    ushort_t *xh, *xl, *w1h, *w1l, *w2h, *w2l, *qh, *ql, *aoh, *aol;
    cudaGetSymbolAddress((void**)&xh,  g_xh);   cudaGetSymbolAddress((void**)&xl,  g_xl);
    cudaGetSymbolAddress((void**)&w1h, g_w1h);  cudaGetSymbolAddress((void**)&w1l, g_w1l);
    cudaGetSymbolAddress((void**)&w2h, g_w2h);  cudaGetSymbolAddress((void**)&w2l, g_w2l);
    cudaGetSymbolAddress((void**)&qh,  g_qkvh); cudaGetSymbolAddress((void**)&ql,  g_qkvl);
    cudaGetSymbolAddress((void**)&aoh, g_aoh);  cudaGetSymbolAddress((void**)&aol, g_aol);

    // 0) split inputs into bf16 hi/lo planes
    const int nx4 = M_ * C_ / 4, nw14 = C3_ * C_ / 4, nw24 = C_ * C_ / 4;
    split_k<<<(nx4 + 255) / 256, 256>>>(x, xh, xl, nx4);
    split_k<<<(nw14 + 255) / 256, 256>>>(qkv_w, w1h, w1l, nw14);
    split_k<<<(nw24 + 255) / 256, 256>>>(proj_w, w2h, w2l, nw24);

    // 1) fused permute + QKV GEMM -> qkv planes
    mma_gemm_k<C3_, 0><<<dim3(C3_ / 128, M_ / 128), 256>>>(
        xh, xl, w1h, w1l, nullptr, qh, ql, nullptr);

    // 2) tensor-core windowed attention -> ao planes
    attn_k<<<B_ * NWIN_ * H_ * 2, 256>>>();

    // 3) proj GEMM, permuted store + bias -> fp32 out
    mma_gemm_k<C_, 1><<<dim3(C_ / 128, M_ / 128), 256>>>(
        aoh, aol, w2h, w2l, proj_b, nullptr, nullptr, out);
}